// round 6
// baseline (speedup 1.0000x reference)
#include <cuda_runtime.h>
#include <cuda_bf16.h>
#include <math.h>

#define NN 100000
#define EE 1600000
#define FIN 64
#define HID 16
#define CC 40

typedef unsigned long long ull;

// ---------------- scratch (static device globals; no allocation) ----------------
__device__ float d_deg[NN];          // weighted in-degree (at dst)
__device__ float d_dinv[NN];         // rsqrt(deg)
__device__ int   d_cnt[NN];          // integer in-degree (histogram)
__device__ int   d_base[NN + 1];     // CSR row offsets
__device__ int   d_cursor[NN];       // bucket write cursors
__device__ ull   d_pack[EE];         // per-edge packed (src:int32, w:f32)
__device__ float d_z0[NN * HID];     // x @ W1[0]
__device__ float d_y1[NN * HID];     // x @ W1[1]; scaled in-place to dinv*y1
__device__ float d_h[NN * HID];      // relu(...) unscaled
__device__ float d_hs[NN * HID];     // dinv * h (gather table for layer 2)

static float* p_deg;  static float* p_dinv;
static int*   p_cnt;  static int*   p_base;  static int* p_cursor;
static ull*   p_pack;
static float* p_z0;   static float* p_y1;    static float* p_h;  static float* p_hs;
static cudaStream_t g_s2;
static cudaEvent_t  g_evA, g_evB;

// ---------------- kernels ----------------
__global__ void k_zero(float* deg, int* cnt, int n) {
    int i = blockIdx.x * blockDim.x + threadIdx.x;
    if (i >= n) return;
    deg[i] = 0.0f;
    cnt[i] = 0;
}

__global__ void k_deg(const int* __restrict__ ei, const float* __restrict__ w,
                      float* deg, int* cnt, int n) {
    int e = blockIdx.x * blockDim.x + threadIdx.x;
    if (e >= n) return;
    int d = ei[EE + e];          // dst = row 1
    atomicAdd(&deg[d], w[e]);
    atomicAdd(&cnt[d], 1);
}

__global__ void k_dinv(const float* __restrict__ deg, float* dinv, int n) {
    int i = blockIdx.x * blockDim.x + threadIdx.x;
    if (i >= n) return;
    float dg = deg[i];
    dinv[i] = (dg > 0.0f) ? rsqrtf(dg) : 0.0f;
}

// Single-block exclusive scan of cnt -> base[0..NN]; cursor = copy.
__global__ void __launch_bounds__(1024, 1)
k_scan(const int* __restrict__ cnt, int* base, int* cursor) {
    const int T = 1024;
    int tid = threadIdx.x;
    const int per = (NN + T - 1) / T;
    int start = tid * per;
    int end = start + per; if (end > NN) end = NN;
    if (start > NN) start = NN;

    int sum = 0;
    for (int i = start; i < end; i++) sum += cnt[i];

    int lane = tid & 31, wid = tid >> 5;
    __shared__ int wsum[32];
    int v = sum;
#pragma unroll
    for (int off = 1; off < 32; off <<= 1) {
        int t = __shfl_up_sync(0xffffffffu, v, off);
        if (lane >= off) v += t;
    }
    if (lane == 31) wsum[wid] = v;
    __syncthreads();
    if (wid == 0) {
        int wv = wsum[lane];
#pragma unroll
        for (int off = 1; off < 32; off <<= 1) {
            int t = __shfl_up_sync(0xffffffffu, wv, off);
            if (lane >= off) wv += t;
        }
        wsum[lane] = wv;
    }
    __syncthreads();
    int run = v - sum + (wid > 0 ? wsum[wid - 1] : 0);
    for (int i = start; i < end; i++) {
        base[i] = run;
        cursor[i] = run;
        run += cnt[i];
    }
    if (start < NN && end == NN) base[NN] = run;
}

// Bucket edges by dst; store (src, w) packed. No dinv dependency.
__global__ void k_bucket(const int* __restrict__ ei, const float* __restrict__ w,
                         int* cursor, ull* pack, int n) {
    int e = blockIdx.x * blockDim.x + threadIdx.x;
    if (e >= n) return;
    int s = ei[e], d = ei[EE + e];
    int pos = atomicAdd(&cursor[d], 1);
    pack[pos] = (ull)(unsigned)s | ((ull)__float_as_uint(w[e]) << 32);
}

// z0 = x@W1[0], y1 = x@W1[1], fused (reads x once). Runs on side stream.
__global__ void __launch_bounds__(128, 1)
k_gemm1(const float* __restrict__ x, const float* __restrict__ W1,
        float* z0g, float* y1g, int n) {
    __shared__ float W0s[FIN * HID];
    __shared__ float W1s[FIN * HID];
    for (int i = threadIdx.x; i < FIN * HID; i += blockDim.x) {
        W0s[i] = W1[i];
        W1s[i] = W1[FIN * HID + i];
    }
    __syncthreads();
    int nd = blockIdx.x * blockDim.x + threadIdx.x;
    if (nd >= n) return;

    float acc0[HID], acc1[HID];
#pragma unroll
    for (int h = 0; h < HID; h++) { acc0[h] = 0.0f; acc1[h] = 0.0f; }

    const float4* xr = reinterpret_cast<const float4*>(x + (size_t)nd * FIN);
#pragma unroll
    for (int k4 = 0; k4 < FIN / 4; k4++) {
        float4 v = xr[k4];
        const float* w0 = &W0s[(k4 * 4) * HID];
        const float* w1 = &W1s[(k4 * 4) * HID];
#pragma unroll
        for (int h = 0; h < HID; h++) {
            acc0[h] += v.x * w0[h] + v.y * w0[HID + h] + v.z * w0[2 * HID + h] + v.w * w0[3 * HID + h];
            acc1[h] += v.x * w1[h] + v.y * w1[HID + h] + v.z * w1[2 * HID + h] + v.w * w1[3 * HID + h];
        }
    }
    float4* z0 = reinterpret_cast<float4*>(z0g + (size_t)nd * HID);
    float4* y1 = reinterpret_cast<float4*>(y1g + (size_t)nd * HID);
#pragma unroll
    for (int q = 0; q < HID / 4; q++) {
        z0[q] = make_float4(acc0[4 * q], acc0[4 * q + 1], acc0[4 * q + 2], acc0[4 * q + 3]);
        y1[q] = make_float4(acc1[4 * q], acc1[4 * q + 1], acc1[4 * q + 2], acc1[4 * q + 3]);
    }
}

// y1 *= dinv[node]  (in-place; gemm1 rewrites y1 every replay before this)
__global__ void k_scale(const float* __restrict__ dinv, float* y1, int n) {
    int i = blockIdx.x * blockDim.x + threadIdx.x;
    if (i >= n) return;
    y1[i] *= dinv[i >> 4];
}

// Gather layer 1: warp per node. Coalesced pack fetch (one edge per lane),
// shuffle-broadcast (src,w) from registers; 16-lane group g handles edges
// 2j+g of each 32-edge chunk. Uniform trip count -> full-mask shuffles legal.
// h = relu(z0 - dinv[nd]*acc + b1);  hs = dinv[nd]*h
__global__ void __launch_bounds__(256, 8)
k_gather1(const int* __restrict__ base, const ull* __restrict__ pack,
          const float* __restrict__ y1s, const float* __restrict__ z0,
          const float* __restrict__ b1, const float* __restrict__ dinv,
          float* __restrict__ h, float* __restrict__ hs, int n) {
    int warp = threadIdx.x >> 5;
    int lane = threadIdx.x & 31;
    int nd = blockIdx.x * 8 + warp;
    if (nd >= n) return;

    int s = base[nd], e = base[nd + 1];
    int g = lane >> 4, f = lane & 15;

    float acc = 0.0f;
    for (int c = s; c < e; c += 32) {
        int idx = c + lane;
        ull p = (idx < e) ? pack[idx] : 0ULL;   // OOB -> src=0, w=0 (adds 0)
        int   srcl = (int)(unsigned)(p & 0xffffffffULL);
        float wl   = __uint_as_float((unsigned)(p >> 32));
        int cnt = e - c; if (cnt > 32) cnt = 32;
        int jmax = (cnt + 1) >> 1;              // warp-uniform
#pragma unroll 4
        for (int j = 0; j < jmax; j++) {
            int sl = 2 * j + g;
            int   src = __shfl_sync(0xffffffffu, srcl, sl);
            float wv  = __shfl_sync(0xffffffffu, wl, sl);
            acc += wv * __ldg(&y1s[(size_t)src * HID + f]);
        }
    }
    acc += __shfl_xor_sync(0xffffffffu, acc, 16);

    if (g == 0) {
        float dv = dinv[nd];
        float v = z0[(size_t)nd * HID + f] - dv * acc + __ldg(&b1[f]);
        v = fmaxf(v, 0.0f);
        h[(size_t)nd * HID + f] = v;
        hs[(size_t)nd * HID + f] = dv * v;
    }
}

// Gather layer 2 fused with final GEMM + log_softmax. Warp per node.
__global__ void __launch_bounds__(256, 8)
k_gather2_final(const int* __restrict__ base, const ull* __restrict__ pack,
                const float* __restrict__ hsg, const float* __restrict__ hg,
                const float* __restrict__ dinv,
                const float* __restrict__ W2, const float* __restrict__ b2,
                float* __restrict__ out, int n) {
    __shared__ float W20s[HID * CC];
    __shared__ float W21s[HID * CC];
    __shared__ float b2s[CC];
    for (int i = threadIdx.x; i < HID * CC; i += blockDim.x) {
        W20s[i] = W2[i];
        W21s[i] = W2[HID * CC + i];
    }
    if (threadIdx.x < CC) b2s[threadIdx.x] = b2[threadIdx.x];
    __syncthreads();

    int warp = threadIdx.x >> 5;
    int lane = threadIdx.x & 31;
    int nd = blockIdx.x * 8 + warp;
    if (nd >= n) return;

    int s = base[nd], e = base[nd + 1];
    int g = lane >> 4;
    int f = lane & 15;

    float acc = 0.0f;
    for (int c = s; c < e; c += 32) {
        int idx = c + lane;
        ull p = (idx < e) ? pack[idx] : 0ULL;
        int   srcl = (int)(unsigned)(p & 0xffffffffULL);
        float wl   = __uint_as_float((unsigned)(p >> 32));
        int cnt = e - c; if (cnt > 32) cnt = 32;
        int jmax = (cnt + 1) >> 1;
#pragma unroll 4
        for (int j = 0; j < jmax; j++) {
            int sl = 2 * j + g;
            int   src = __shfl_sync(0xffffffffu, srcl, sl);
            float wv  = __shfl_sync(0xffffffffu, wl, sl);
            acc += wv * __ldg(&hsg[(size_t)src * HID + f]);
        }
    }
    acc += __shfl_xor_sync(0xffffffffu, acc, 16);
    acc *= -dinv[nd];          // Tx1 feature (lane&15) now in all lanes

    const float* hp = hg + (size_t)nd * HID;
    float oa = b2s[lane];                               // class = lane
    float ob = (lane < CC - 32) ? b2s[32 + lane] : 0.f; // class = lane+32
#pragma unroll
    for (int ff = 0; ff < HID; ff++) {
        float hf = hp[ff];                               // warp-uniform broadcast
        float af = __shfl_sync(0xffffffffu, acc, ff);    // lane ff holds feature ff
        oa += hf * W20s[ff * CC + lane] + af * W21s[ff * CC + lane];
        if (lane < CC - 32)
            ob += hf * W20s[ff * CC + 32 + lane] + af * W21s[ff * CC + 32 + lane];
    }

    float m = (lane < CC - 32) ? fmaxf(oa, ob) : oa;
#pragma unroll
    for (int off = 16; off > 0; off >>= 1)
        m = fmaxf(m, __shfl_xor_sync(0xffffffffu, m, off));

    float sexp = expf(oa - m) + ((lane < CC - 32) ? expf(ob - m) : 0.0f);
#pragma unroll
    for (int off = 16; off > 0; off >>= 1)
        sexp += __shfl_xor_sync(0xffffffffu, sexp, off);

    float lse = logf(sexp) + m;

    float* op = out + (size_t)nd * CC;
    op[lane] = oa - lse;
    if (lane < CC - 32) op[32 + lane] = ob - lse;
}

// ---------------- prewarm ----------------
namespace {
struct Prewarm {
    Prewarm() {
        void* p;
        cudaGetSymbolAddress(&p, d_deg);    p_deg    = (float*)p;
        cudaGetSymbolAddress(&p, d_dinv);   p_dinv   = (float*)p;
        cudaGetSymbolAddress(&p, d_cnt);    p_cnt    = (int*)p;
        cudaGetSymbolAddress(&p, d_base);   p_base   = (int*)p;
        cudaGetSymbolAddress(&p, d_cursor); p_cursor = (int*)p;
        cudaGetSymbolAddress(&p, d_pack);   p_pack   = (ull*)p;
        cudaGetSymbolAddress(&p, d_z0);     p_z0     = (float*)p;
        cudaGetSymbolAddress(&p, d_y1);     p_y1     = (float*)p;
        cudaGetSymbolAddress(&p, d_h);      p_h      = (float*)p;
        cudaGetSymbolAddress(&p, d_hs);     p_hs     = (float*)p;

        cudaStreamCreateWithFlags(&g_s2, cudaStreamNonBlocking);
        cudaEventCreateWithFlags(&g_evA, cudaEventDisableTiming);
        cudaEventCreateWithFlags(&g_evB, cudaEventDisableTiming);

        // Degenerate launches to force module/code load + lmem pool sizing
        // before the harness checkpoint. All pointers valid; n=0 guards.
        const int*   di = (const int*)p_cnt;
        const float* df = (const float*)p_z0;
        k_zero<<<1, 32>>>(p_deg, p_cnt, 0);
        k_deg<<<1, 32>>>(di, df, p_deg, p_cnt, 0);
        k_dinv<<<1, 32>>>(p_deg, p_dinv, 0);
        k_scan<<<1, 1024>>>(p_cnt, p_base, p_cursor);
        k_bucket<<<1, 32>>>(di, df, p_cursor, p_pack, 0);
        k_gemm1<<<1, 128, 0, g_s2>>>(df, df, p_z0, p_y1, 0);
        k_scale<<<1, 32>>>(p_dinv, p_y1, 0);
        k_gather1<<<1, 256>>>(p_base, p_pack, p_y1, p_z0, df, p_dinv, p_h, p_hs, 0);
        k_gather2_final<<<1, 256>>>(p_base, p_pack, p_hs, p_h, p_dinv, df, df, p_z0, 0);
        cudaDeviceSynchronize();
    }
};
Prewarm g_prewarm;
}  // namespace

// ---------------- launch ----------------
extern "C" void kernel_launch(void* const* d_in, const int* in_sizes, int n_in,
                              void* d_out, int out_size) {
    const float* x  = (const float*)d_in[0];
    const float* w  = (const float*)d_in[1];
    const float* W1 = (const float*)d_in[2];
    const float* b1 = (const float*)d_in[3];
    const float* W2 = (const float*)d_in[4];
    const float* b2 = (const float*)d_in[5];
    const int*   ei = (const int*)d_in[6];
    float* out = (float*)d_out;

    const int T = 256;

    // Fork: gemm1 on side stream (independent of graph-structure chain).
    cudaEventRecord(g_evA, 0);
    cudaStreamWaitEvent(g_s2, g_evA, 0);
    k_gemm1<<<(NN + 127) / 128, 128, 0, g_s2>>>(x, W1, p_z0, p_y1, NN);
    cudaEventRecord(g_evB, g_s2);

    // Main chain: structure + degrees.
    k_zero<<<(NN + T - 1) / T, T>>>(p_deg, p_cnt, NN);
    k_deg<<<(EE + T - 1) / T, T>>>(ei, w, p_deg, p_cnt, EE);
    k_dinv<<<(NN + T - 1) / T, T>>>(p_deg, p_dinv, NN);
    k_scan<<<1, 1024>>>(p_cnt, p_base, p_cursor);
    k_bucket<<<(EE + T - 1) / T, T>>>(ei, w, p_cursor, p_pack, EE);

    // Join, then scale y1 by dinv and gather.
    cudaStreamWaitEvent(0, g_evB, 0);
    k_scale<<<(NN * HID + T - 1) / T, T>>>(p_dinv, p_y1, NN * HID);
    k_gather1<<<(NN + 7) / 8, 256>>>(p_base, p_pack, p_y1, p_z0, b1, p_dinv, p_h, p_hs, NN);
    k_gather2_final<<<(NN + 7) / 8, 256>>>(p_base, p_pack, p_hs, p_h, p_dinv, W2, b2, out, NN);
}

// round 7
// speedup vs baseline: 1.9133x; 1.9133x over previous
#include <cuda_runtime.h>
#include <cuda_bf16.h>
#include <math.h>

#define NN 100000
#define EE 1600000
#define FIN 64
#define HID 16
#define CC 40

typedef unsigned long long ull;

// ---------------- scratch (static device globals; no allocation) ----------------
__device__ float d_deg[NN];          // weighted in-degree (at dst)
__device__ float d_dinv[NN];         // rsqrt(deg)
__device__ int   d_cnt[NN];          // integer in-degree (histogram)
__device__ int   d_base[NN];         // bucket start offset (permuted CSR)
__device__ int   d_cursor[NN];       // bucket write cursors
__device__ int   d_total[1];         // global bucket allocator
__device__ ull   d_pack[EE];         // per-edge packed (src:int32, w:f32)
__device__ float d_z0[NN * HID];     // x @ W1[0]
__device__ float d_y1[NN * HID];     // dinv * (x @ W1[1])  (pre-scaled)
__device__ float d_h[NN * HID];      // relu(...) unscaled
__device__ float d_hs[NN * HID];     // dinv * h (gather table for layer 2)

static float* p_deg;  static float* p_dinv;
static int*   p_cnt;  static int*   p_base;  static int* p_cursor; static int* p_total;
static ull*   p_pack;
static float* p_z0;   static float* p_y1;    static float* p_h;  static float* p_hs;
static cudaStream_t g_s2;
static cudaEvent_t  g_evA, g_evB;

// ---------------- kernels ----------------
__global__ void k_zero(float* deg, int* cnt, int* total, int n) {
    int i = blockIdx.x * blockDim.x + threadIdx.x;
    if (i == 0) total[0] = 0;
    if (i >= n) return;
    deg[i] = 0.0f;
    cnt[i] = 0;
}

__global__ void k_deg(const int* __restrict__ ei, const float* __restrict__ w,
                      float* deg, int* cnt, int n) {
    int e = blockIdx.x * blockDim.x + threadIdx.x;
    if (e >= n) return;
    int d = ei[EE + e];          // dst = row 1
    atomicAdd(&deg[d], w[e]);
    atomicAdd(&cnt[d], 1);
}

// Parallel bucket assignment: block-local scan of cnt + one atomicAdd per block
// on the global allocator. Bucket layout is permuted vs node order - harmless,
// gather uses [base[nd], base[nd]+cnt[nd]). Also computes dinv here.
__global__ void __launch_bounds__(256, 8)
k_assign(const int* __restrict__ cnt, const float* __restrict__ deg,
         int* base, int* cursor, float* dinv, int* total, int n) {
    int tid = threadIdx.x;
    int i = blockIdx.x * 256 + tid;
    int c = (i < n) ? cnt[i] : 0;

    int lane = tid & 31, wid = tid >> 5;
    __shared__ int ws[8];
    __shared__ int bbase;

    int v = c;
#pragma unroll
    for (int off = 1; off < 32; off <<= 1) {
        int t = __shfl_up_sync(0xffffffffu, v, off);
        if (lane >= off) v += t;
    }
    if (lane == 31) ws[wid] = v;
    __syncthreads();
    if (wid == 0 && lane < 8) {
        int wv = ws[lane];
#pragma unroll
        for (int off = 1; off < 8; off <<= 1) {
            int t = __shfl_up_sync(0x000000ffu, wv, off);
            if (lane >= off) wv += t;
        }
        ws[lane] = wv;
    }
    __syncthreads();
    if (tid == 0) bbase = atomicAdd(total, ws[7]);
    __syncthreads();

    if (i < n) {
        int excl = v - c + (wid > 0 ? ws[wid - 1] : 0);
        int b = bbase + excl;
        base[i] = b;
        cursor[i] = b;
        float dg = deg[i];
        dinv[i] = (dg > 0.0f) ? rsqrtf(dg) : 0.0f;
    }
}

// Bucket edges by dst; store (src, w) packed. No dinv dependency.
__global__ void k_bucket(const int* __restrict__ ei, const float* __restrict__ w,
                         int* cursor, ull* pack, int n) {
    int e = blockIdx.x * blockDim.x + threadIdx.x;
    if (e >= n) return;
    int s = ei[e], d = ei[EE + e];
    int pos = atomicAdd(&cursor[d], 1);
    pack[pos] = (ull)(unsigned)s | ((ull)__float_as_uint(w[e]) << 32);
}

// z0 = x@W1[0], y1s = dinv*(x@W1[1]), fused (reads x once). Side stream,
// waits for dinv (k_assign event).
__global__ void __launch_bounds__(128, 1)
k_gemm1(const float* __restrict__ x, const float* __restrict__ W1,
        const float* __restrict__ dinv, float* z0g, float* y1g, int n) {
    __shared__ float W0s[FIN * HID];
    __shared__ float W1s[FIN * HID];
    for (int i = threadIdx.x; i < FIN * HID; i += blockDim.x) {
        W0s[i] = W1[i];
        W1s[i] = W1[FIN * HID + i];
    }
    __syncthreads();
    int nd = blockIdx.x * blockDim.x + threadIdx.x;
    if (nd >= n) return;

    float acc0[HID], acc1[HID];
#pragma unroll
    for (int h = 0; h < HID; h++) { acc0[h] = 0.0f; acc1[h] = 0.0f; }

    const float4* xr = reinterpret_cast<const float4*>(x + (size_t)nd * FIN);
#pragma unroll
    for (int k4 = 0; k4 < FIN / 4; k4++) {
        float4 v = xr[k4];
        const float* w0 = &W0s[(k4 * 4) * HID];
        const float* w1 = &W1s[(k4 * 4) * HID];
#pragma unroll
        for (int h = 0; h < HID; h++) {
            acc0[h] += v.x * w0[h] + v.y * w0[HID + h] + v.z * w0[2 * HID + h] + v.w * w0[3 * HID + h];
            acc1[h] += v.x * w1[h] + v.y * w1[HID + h] + v.z * w1[2 * HID + h] + v.w * w1[3 * HID + h];
        }
    }
    float dv = dinv[nd];
    float4* z0 = reinterpret_cast<float4*>(z0g + (size_t)nd * HID);
    float4* y1 = reinterpret_cast<float4*>(y1g + (size_t)nd * HID);
#pragma unroll
    for (int q = 0; q < HID / 4; q++) {
        z0[q] = make_float4(acc0[4 * q], acc0[4 * q + 1], acc0[4 * q + 2], acc0[4 * q + 3]);
        y1[q] = make_float4(dv * acc1[4 * q], dv * acc1[4 * q + 1],
                            dv * acc1[4 * q + 2], dv * acc1[4 * q + 3]);
    }
}

// Gather layer 1: warp per node. Coalesced pack fetch (one edge per lane),
// shuffle-broadcast (src,w); 16-lane group g handles edges 2j+g of each chunk.
// h = relu(z0 - dinv[nd]*acc + b1);  hs = dinv[nd]*h
__global__ void __launch_bounds__(256, 8)
k_gather1(const int* __restrict__ base, const int* __restrict__ cnt,
          const ull* __restrict__ pack,
          const float* __restrict__ y1s, const float* __restrict__ z0,
          const float* __restrict__ b1, const float* __restrict__ dinv,
          float* __restrict__ h, float* __restrict__ hs, int n) {
    int warp = threadIdx.x >> 5;
    int lane = threadIdx.x & 31;
    int nd = blockIdx.x * 8 + warp;
    if (nd >= n) return;

    int s = base[nd], e = s + cnt[nd];
    int g = lane >> 4, f = lane & 15;

    float acc = 0.0f;
    for (int c = s; c < e; c += 32) {
        int idx = c + lane;
        ull p = (idx < e) ? pack[idx] : 0ULL;   // OOB -> src=0, w=0 (adds 0)
        int   srcl = (int)(unsigned)(p & 0xffffffffULL);
        float wl   = __uint_as_float((unsigned)(p >> 32));
        int rem = e - c; if (rem > 32) rem = 32;
        int jmax = (rem + 1) >> 1;              // warp-uniform
#pragma unroll 4
        for (int j = 0; j < jmax; j++) {
            int sl = 2 * j + g;
            int   src = __shfl_sync(0xffffffffu, srcl, sl);
            float wv  = __shfl_sync(0xffffffffu, wl, sl);
            acc += wv * __ldg(&y1s[(size_t)src * HID + f]);
        }
    }
    acc += __shfl_xor_sync(0xffffffffu, acc, 16);

    if (g == 0) {
        float dv = dinv[nd];
        float v = z0[(size_t)nd * HID + f] - dv * acc + __ldg(&b1[f]);
        v = fmaxf(v, 0.0f);
        h[(size_t)nd * HID + f] = v;
        hs[(size_t)nd * HID + f] = dv * v;
    }
}

// Gather layer 2 fused with final GEMM + log_softmax. Warp per node.
__global__ void __launch_bounds__(256, 8)
k_gather2_final(const int* __restrict__ base, const int* __restrict__ cnt,
                const ull* __restrict__ pack,
                const float* __restrict__ hsg, const float* __restrict__ hg,
                const float* __restrict__ dinv,
                const float* __restrict__ W2, const float* __restrict__ b2,
                float* __restrict__ out, int n) {
    __shared__ float W20s[HID * CC];
    __shared__ float W21s[HID * CC];
    __shared__ float b2s[CC];
    for (int i = threadIdx.x; i < HID * CC; i += blockDim.x) {
        W20s[i] = W2[i];
        W21s[i] = W2[HID * CC + i];
    }
    if (threadIdx.x < CC) b2s[threadIdx.x] = b2[threadIdx.x];
    __syncthreads();

    int warp = threadIdx.x >> 5;
    int lane = threadIdx.x & 31;
    int nd = blockIdx.x * 8 + warp;
    if (nd >= n) return;

    int s = base[nd], e = s + cnt[nd];
    int g = lane >> 4, f = lane & 15;

    float acc = 0.0f;
    for (int c = s; c < e; c += 32) {
        int idx = c + lane;
        ull p = (idx < e) ? pack[idx] : 0ULL;
        int   srcl = (int)(unsigned)(p & 0xffffffffULL);
        float wl   = __uint_as_float((unsigned)(p >> 32));
        int rem = e - c; if (rem > 32) rem = 32;
        int jmax = (rem + 1) >> 1;
#pragma unroll 4
        for (int j = 0; j < jmax; j++) {
            int sl = 2 * j + g;
            int   src = __shfl_sync(0xffffffffu, srcl, sl);
            float wv  = __shfl_sync(0xffffffffu, wl, sl);
            acc += wv * __ldg(&hsg[(size_t)src * HID + f]);
        }
    }
    acc += __shfl_xor_sync(0xffffffffu, acc, 16);
    acc *= -dinv[nd];          // Tx1 feature (lane&15) now in all lanes

    const float* hp = hg + (size_t)nd * HID;
    float oa = b2s[lane];                               // class = lane
    float ob = (lane < CC - 32) ? b2s[32 + lane] : 0.f; // class = lane+32
#pragma unroll
    for (int ff = 0; ff < HID; ff++) {
        float hf = hp[ff];                               // warp-uniform broadcast
        float af = __shfl_sync(0xffffffffu, acc, ff);    // lane ff holds feature ff
        oa += hf * W20s[ff * CC + lane] + af * W21s[ff * CC + lane];
        if (lane < CC - 32)
            ob += hf * W20s[ff * CC + 32 + lane] + af * W21s[ff * CC + 32 + lane];
    }

    float m = (lane < CC - 32) ? fmaxf(oa, ob) : oa;
#pragma unroll
    for (int off = 16; off > 0; off >>= 1)
        m = fmaxf(m, __shfl_xor_sync(0xffffffffu, m, off));

    float sexp = expf(oa - m) + ((lane < CC - 32) ? expf(ob - m) : 0.0f);
#pragma unroll
    for (int off = 16; off > 0; off >>= 1)
        sexp += __shfl_xor_sync(0xffffffffu, sexp, off);

    float lse = logf(sexp) + m;

    float* op = out + (size_t)nd * CC;
    op[lane] = oa - lse;
    if (lane < CC - 32) op[32 + lane] = ob - lse;
}

// ---------------- prewarm ----------------
namespace {
struct Prewarm {
    Prewarm() {
        void* p;
        cudaGetSymbolAddress(&p, d_deg);    p_deg    = (float*)p;
        cudaGetSymbolAddress(&p, d_dinv);   p_dinv   = (float*)p;
        cudaGetSymbolAddress(&p, d_cnt);    p_cnt    = (int*)p;
        cudaGetSymbolAddress(&p, d_base);   p_base   = (int*)p;
        cudaGetSymbolAddress(&p, d_cursor); p_cursor = (int*)p;
        cudaGetSymbolAddress(&p, d_total);  p_total  = (int*)p;
        cudaGetSymbolAddress(&p, d_pack);   p_pack   = (ull*)p;
        cudaGetSymbolAddress(&p, d_z0);     p_z0     = (float*)p;
        cudaGetSymbolAddress(&p, d_y1);     p_y1     = (float*)p;
        cudaGetSymbolAddress(&p, d_h);      p_h      = (float*)p;
        cudaGetSymbolAddress(&p, d_hs);     p_hs     = (float*)p;

        cudaStreamCreateWithFlags(&g_s2, cudaStreamNonBlocking);
        cudaEventCreateWithFlags(&g_evA, cudaEventDisableTiming);
        cudaEventCreateWithFlags(&g_evB, cudaEventDisableTiming);

        // Degenerate launches to force module/code load + lmem pool sizing
        // before the harness checkpoint. All pointers valid; n=0 guards.
        const int*   di = (const int*)p_cnt;
        const float* df = (const float*)p_z0;
        k_zero<<<1, 32>>>(p_deg, p_cnt, p_total, 0);
        k_deg<<<1, 32>>>(di, df, p_deg, p_cnt, 0);
        k_assign<<<1, 256>>>(p_cnt, p_deg, p_base, p_cursor, p_dinv, p_total, 0);
        k_bucket<<<1, 32>>>(di, df, p_cursor, p_pack, 0);
        k_gemm1<<<1, 128, 0, g_s2>>>(df, df, p_dinv, p_z0, p_y1, 0);
        k_gather1<<<1, 256>>>(p_base, p_cnt, p_pack, p_y1, p_z0, df, p_dinv, p_h, p_hs, 0);
        k_gather2_final<<<1, 256>>>(p_base, p_cnt, p_pack, p_hs, p_h, p_dinv, df, df, p_z0, 0);
        cudaDeviceSynchronize();
    }
};
Prewarm g_prewarm;
}  // namespace

// ---------------- launch ----------------
extern "C" void kernel_launch(void* const* d_in, const int* in_sizes, int n_in,
                              void* d_out, int out_size) {
    const float* x  = (const float*)d_in[0];
    const float* w  = (const float*)d_in[1];
    const float* W1 = (const float*)d_in[2];
    const float* b1 = (const float*)d_in[3];
    const float* W2 = (const float*)d_in[4];
    const float* b2 = (const float*)d_in[5];
    const int*   ei = (const int*)d_in[6];
    float* out = (float*)d_out;

    const int T = 256;

    // Main chain: structure + degrees + bucket assignment.
    k_zero<<<(NN + T - 1) / T, T>>>(p_deg, p_cnt, p_total, NN);
    k_deg<<<(EE + T - 1) / T, T>>>(ei, w, p_deg, p_cnt, EE);
    k_assign<<<(NN + 255) / 256, 256>>>(p_cnt, p_deg, p_base, p_cursor, p_dinv, p_total, NN);

    // Fork: gemm1 (needs dinv) runs on side stream, overlapping k_bucket.
    cudaEventRecord(g_evA, 0);
    cudaStreamWaitEvent(g_s2, g_evA, 0);
    k_gemm1<<<(NN + 127) / 128, 128, 0, g_s2>>>(x, W1, p_dinv, p_z0, p_y1, NN);
    cudaEventRecord(g_evB, g_s2);

    k_bucket<<<(EE + T - 1) / T, T>>>(ei, w, p_cursor, p_pack, EE);

    // Join, then gather.
    cudaStreamWaitEvent(0, g_evB, 0);
    k_gather1<<<(NN + 7) / 8, 256>>>(p_base, p_cnt, p_pack, p_y1, p_z0, b1, p_dinv, p_h, p_hs, NN);
    k_gather2_final<<<(NN + 7) / 8, 256>>>(p_base, p_cnt, p_pack, p_hs, p_h, p_dinv, W2, b2, out, NN);
}

// round 8
// speedup vs baseline: 1.9437x; 1.0159x over previous
#include <cuda_runtime.h>
#include <cuda_bf16.h>
#include <math.h>

#define NN 100000
#define EE 1600000
#define FIN 64
#define HID 16
#define CC 40

typedef unsigned long long ull;

#define DEG_SCALE 33554432.0f   // 2^25 fixed-point for weighted degree
#define DEG_INV   (1.0f / 33554432.0f)

// ---------------- scratch (static device globals; no allocation) ----------------
__device__ ull   d_degcnt[NN];       // (cnt:int32 << 32) | fixed25(sum w)
__device__ float d_dinv[NN];         // rsqrt(deg)
__device__ int   d_base[NN];         // bucket start offset (permuted CSR)
__device__ int   d_cursor[NN];       // bucket write cursors (end ptr after bucket)
__device__ int   d_total[1];         // global bucket allocator
__device__ ull   d_pack[EE];         // per-edge packed (src:int32, norm:f32)
__device__ float d_z0[NN * HID];     // x @ W1[0]
__device__ float d_y1[NN * HID];     // x @ W1[1]
__device__ float d_h[NN * HID];      // relu(z0 + agg1 + b1)

static ull*   p_degcnt;
static float* p_dinv;
static int*   p_base;  static int* p_cursor; static int* p_total;
static ull*   p_pack;
static float* p_z0;    static float* p_y1;   static float* p_h;
static cudaStream_t g_s2;
static cudaEvent_t  g_evA, g_evB;

// ---------------- kernels ----------------
// One fused 64-bit atomic per edge: cnt++ (hi32), deg += fixed25(w) (lo32).
// 2 edges per thread via int2/float2 loads.
__global__ void k_deg(const int* __restrict__ ei, const float* __restrict__ w,
                      ull* degcnt, int* total, int n2) {
    int t = blockIdx.x * blockDim.x + threadIdx.x;
    if (t == 0) total[0] = 0;
    if (t >= n2) return;
    int2   dd = reinterpret_cast<const int2*>(ei + EE)[t];   // dst row
    float2 ww = reinterpret_cast<const float2*>(w)[t];
    ull a0 = (1ULL << 32) | (ull)__float2uint_rn(ww.x * DEG_SCALE);
    ull a1 = (1ULL << 32) | (ull)__float2uint_rn(ww.y * DEG_SCALE);
    atomicAdd(&degcnt[dd.x], a0);
    atomicAdd(&degcnt[dd.y], a1);
}

// Parallel bucket assignment: block-local scan of cnt + one atomicAdd per block
// on the global allocator. Also computes dinv (decoded from fixed point).
__global__ void __launch_bounds__(256, 8)
k_assign(const ull* __restrict__ degcnt,
         int* base, int* cursor, float* dinv, int* total, int n) {
    int tid = threadIdx.x;
    int i = blockIdx.x * 256 + tid;
    ull dc = (i < n) ? degcnt[i] : 0ULL;
    int c = (int)(dc >> 32);

    int lane = tid & 31, wid = tid >> 5;
    __shared__ int ws[8];
    __shared__ int bbase;

    int v = c;
#pragma unroll
    for (int off = 1; off < 32; off <<= 1) {
        int t = __shfl_up_sync(0xffffffffu, v, off);
        if (lane >= off) v += t;
    }
    if (lane == 31) ws[wid] = v;
    __syncthreads();
    if (wid == 0 && lane < 8) {
        int wv = ws[lane];
#pragma unroll
        for (int off = 1; off < 8; off <<= 1) {
            int t = __shfl_up_sync(0x000000ffu, wv, off);
            if (lane >= off) wv += t;
        }
        ws[lane] = wv;
    }
    __syncthreads();
    if (tid == 0) bbase = atomicAdd(total, ws[7]);
    __syncthreads();

    if (i < n) {
        int excl = v - c + (wid > 0 ? ws[wid - 1] : 0);
        int b = bbase + excl;
        base[i] = b;
        cursor[i] = b;
        float dg = (float)(unsigned)(dc & 0xffffffffULL) * DEG_INV;
        dinv[i] = (dg > 0.0f) ? rsqrtf(dg) : 0.0f;
    }
}

// Bucket edges by dst; store (src, norm) packed. norm = -dinv[s]*w*dinv[d].
// 2 edges per thread.
__global__ void k_bucket(const int* __restrict__ ei, const float* __restrict__ w,
                         const float* __restrict__ dinv,
                         int* cursor, ull* pack, int n2) {
    int t = blockIdx.x * blockDim.x + threadIdx.x;
    if (t >= n2) return;
    int2   ss = reinterpret_cast<const int2*>(ei)[t];        // src row
    int2   dd = reinterpret_cast<const int2*>(ei + EE)[t];   // dst row
    float2 ww = reinterpret_cast<const float2*>(w)[t];
    float n0 = -dinv[ss.x] * ww.x * dinv[dd.x];
    float n1 = -dinv[ss.y] * ww.y * dinv[dd.y];
    int pos0 = atomicAdd(&cursor[dd.x], 1);
    pack[pos0] = (ull)(unsigned)ss.x | ((ull)__float_as_uint(n0) << 32);
    int pos1 = atomicAdd(&cursor[dd.y], 1);
    pack[pos1] = (ull)(unsigned)ss.y | ((ull)__float_as_uint(n1) << 32);
}

// z0 = x@W1[0], y1 = x@W1[1], fused (reads x once). Fully independent ->
// forked on side stream at t=0, hidden under the structure chain.
__global__ void __launch_bounds__(128, 1)
k_gemm1(const float* __restrict__ x, const float* __restrict__ W1,
        float* z0g, float* y1g, int n) {
    __shared__ float W0s[FIN * HID];
    __shared__ float W1s[FIN * HID];
    for (int i = threadIdx.x; i < FIN * HID; i += blockDim.x) {
        W0s[i] = W1[i];
        W1s[i] = W1[FIN * HID + i];
    }
    __syncthreads();
    int nd = blockIdx.x * blockDim.x + threadIdx.x;
    if (nd >= n) return;

    float acc0[HID], acc1[HID];
#pragma unroll
    for (int h = 0; h < HID; h++) { acc0[h] = 0.0f; acc1[h] = 0.0f; }

    const float4* xr = reinterpret_cast<const float4*>(x + (size_t)nd * FIN);
#pragma unroll
    for (int k4 = 0; k4 < FIN / 4; k4++) {
        float4 v = xr[k4];
        const float* w0 = &W0s[(k4 * 4) * HID];
        const float* w1 = &W1s[(k4 * 4) * HID];
#pragma unroll
        for (int h = 0; h < HID; h++) {
            acc0[h] += v.x * w0[h] + v.y * w0[HID + h] + v.z * w0[2 * HID + h] + v.w * w0[3 * HID + h];
            acc1[h] += v.x * w1[h] + v.y * w1[HID + h] + v.z * w1[2 * HID + h] + v.w * w1[3 * HID + h];
        }
    }
    float4* z0 = reinterpret_cast<float4*>(z0g + (size_t)nd * HID);
    float4* y1 = reinterpret_cast<float4*>(y1g + (size_t)nd * HID);
#pragma unroll
    for (int q = 0; q < HID / 4; q++) {
        z0[q] = make_float4(acc0[4 * q], acc0[4 * q + 1], acc0[4 * q + 2], acc0[4 * q + 3]);
        y1[q] = make_float4(acc1[4 * q], acc1[4 * q + 1], acc1[4 * q + 2], acc1[4 * q + 3]);
    }
}

// Gather layer 1: warp per node. Coalesced pack fetch (one edge per lane),
// shuffle-broadcast (src,norm); 16-lane group g handles edges 2j+g.
// h = relu(z0 + sum norm*y1[src] + b1)
__global__ void __launch_bounds__(256, 8)
k_gather1(const int* __restrict__ base, const int* __restrict__ endp,
          const ull* __restrict__ pack,
          const float* __restrict__ y1, const float* __restrict__ z0,
          const float* __restrict__ b1, float* __restrict__ h, int n) {
    int warp = threadIdx.x >> 5;
    int lane = threadIdx.x & 31;
    int nd = blockIdx.x * 8 + warp;
    if (nd >= n) return;

    int s = base[nd], e = endp[nd];   // endp = cursor after bucket = base+cnt
    int g = lane >> 4, f = lane & 15;

    float acc = 0.0f;
    for (int c = s; c < e; c += 32) {
        int idx = c + lane;
        ull p = (idx < e) ? pack[idx] : 0ULL;   // OOB -> src=0, norm=0
        int   srcl = (int)(unsigned)(p & 0xffffffffULL);
        float wl   = __uint_as_float((unsigned)(p >> 32));
        int rem = e - c; if (rem > 32) rem = 32;
        int jmax = (rem + 1) >> 1;              // warp-uniform
#pragma unroll 4
        for (int j = 0; j < jmax; j++) {
            int sl = 2 * j + g;
            int   src = __shfl_sync(0xffffffffu, srcl, sl);
            float wv  = __shfl_sync(0xffffffffu, wl, sl);
            acc += wv * __ldg(&y1[(size_t)src * HID + f]);
        }
    }
    acc += __shfl_xor_sync(0xffffffffu, acc, 16);

    if (g == 0) {
        float v = z0[(size_t)nd * HID + f] + acc + __ldg(&b1[f]);
        h[(size_t)nd * HID + f] = fmaxf(v, 0.0f);
    }
}

// Gather layer 2 fused with final GEMM + log_softmax. Warp per node.
__global__ void __launch_bounds__(256, 8)
k_gather2_final(const int* __restrict__ base, const int* __restrict__ endp,
                const ull* __restrict__ pack, const float* __restrict__ hg,
                const float* __restrict__ W2, const float* __restrict__ b2,
                float* __restrict__ out, int n) {
    __shared__ float W20s[HID * CC];
    __shared__ float W21s[HID * CC];
    __shared__ float b2s[CC];
    for (int i = threadIdx.x; i < HID * CC; i += blockDim.x) {
        W20s[i] = W2[i];
        W21s[i] = W2[HID * CC + i];
    }
    if (threadIdx.x < CC) b2s[threadIdx.x] = b2[threadIdx.x];
    __syncthreads();

    int warp = threadIdx.x >> 5;
    int lane = threadIdx.x & 31;
    int nd = blockIdx.x * 8 + warp;
    if (nd >= n) return;

    int s = base[nd], e = endp[nd];
    int g = lane >> 4, f = lane & 15;

    float acc = 0.0f;
    for (int c = s; c < e; c += 32) {
        int idx = c + lane;
        ull p = (idx < e) ? pack[idx] : 0ULL;
        int   srcl = (int)(unsigned)(p & 0xffffffffULL);
        float wl   = __uint_as_float((unsigned)(p >> 32));
        int rem = e - c; if (rem > 32) rem = 32;
        int jmax = (rem + 1) >> 1;
#pragma unroll 4
        for (int j = 0; j < jmax; j++) {
            int sl = 2 * j + g;
            int   src = __shfl_sync(0xffffffffu, srcl, sl);
            float wv  = __shfl_sync(0xffffffffu, wl, sl);
            acc += wv * __ldg(&hg[(size_t)src * HID + f]);
        }
    }
    acc += __shfl_xor_sync(0xffffffffu, acc, 16);   // Tx1 feature f in all lanes

    const float* hp = hg + (size_t)nd * HID;
    float oa = b2s[lane];                               // class = lane
    float ob = (lane < CC - 32) ? b2s[32 + lane] : 0.f; // class = lane+32
#pragma unroll
    for (int ff = 0; ff < HID; ff++) {
        float hf = hp[ff];                               // warp-uniform broadcast
        float af = __shfl_sync(0xffffffffu, acc, ff);    // lane ff holds feature ff
        oa += hf * W20s[ff * CC + lane] + af * W21s[ff * CC + lane];
        if (lane < CC - 32)
            ob += hf * W20s[ff * CC + 32 + lane] + af * W21s[ff * CC + 32 + lane];
    }

    float m = (lane < CC - 32) ? fmaxf(oa, ob) : oa;
#pragma unroll
    for (int off = 16; off > 0; off >>= 1)
        m = fmaxf(m, __shfl_xor_sync(0xffffffffu, m, off));

    float sexp = expf(oa - m) + ((lane < CC - 32) ? expf(ob - m) : 0.0f);
#pragma unroll
    for (int off = 16; off > 0; off >>= 1)
        sexp += __shfl_xor_sync(0xffffffffu, sexp, off);

    float lse = logf(sexp) + m;

    float* op = out + (size_t)nd * CC;
    op[lane] = oa - lse;
    if (lane < CC - 32) op[32 + lane] = ob - lse;
}

// ---------------- prewarm ----------------
namespace {
struct Prewarm {
    Prewarm() {
        void* p;
        cudaGetSymbolAddress(&p, d_degcnt); p_degcnt = (ull*)p;
        cudaGetSymbolAddress(&p, d_dinv);   p_dinv   = (float*)p;
        cudaGetSymbolAddress(&p, d_base);   p_base   = (int*)p;
        cudaGetSymbolAddress(&p, d_cursor); p_cursor = (int*)p;
        cudaGetSymbolAddress(&p, d_total);  p_total  = (int*)p;
        cudaGetSymbolAddress(&p, d_pack);   p_pack   = (ull*)p;
        cudaGetSymbolAddress(&p, d_z0);     p_z0     = (float*)p;
        cudaGetSymbolAddress(&p, d_y1);     p_y1     = (float*)p;
        cudaGetSymbolAddress(&p, d_h);      p_h      = (float*)p;

        cudaStreamCreateWithFlags(&g_s2, cudaStreamNonBlocking);
        cudaEventCreateWithFlags(&g_evA, cudaEventDisableTiming);
        cudaEventCreateWithFlags(&g_evB, cudaEventDisableTiming);

        // Degenerate launches to force module/code load + lmem pool sizing
        // before the harness checkpoint. All pointers valid; n=0 guards.
        const int*   di = (const int*)p_base;
        const float* df = (const float*)p_z0;
        cudaMemsetAsync(p_degcnt, 0, NN * sizeof(ull), 0);
        k_deg<<<1, 32>>>(di, df, p_degcnt, p_total, 0);
        k_assign<<<1, 256>>>(p_degcnt, p_base, p_cursor, p_dinv, p_total, 0);
        k_bucket<<<1, 32>>>(di, df, p_dinv, p_cursor, p_pack, 0);
        k_gemm1<<<1, 128, 0, g_s2>>>(df, df, p_z0, p_y1, 0);
        k_gather1<<<1, 256>>>(p_base, p_cursor, p_pack, p_y1, p_z0, df, p_h, 0);
        k_gather2_final<<<1, 256>>>(p_base, p_cursor, p_pack, p_h, df, df, p_z0, 0);
        cudaDeviceSynchronize();
    }
};
Prewarm g_prewarm;
}  // namespace

// ---------------- launch ----------------
extern "C" void kernel_launch(void* const* d_in, const int* in_sizes, int n_in,
                              void* d_out, int out_size) {
    const float* x  = (const float*)d_in[0];
    const float* w  = (const float*)d_in[1];
    const float* W1 = (const float*)d_in[2];
    const float* b1 = (const float*)d_in[3];
    const float* W2 = (const float*)d_in[4];
    const float* b2 = (const float*)d_in[5];
    const int*   ei = (const int*)d_in[6];
    float* out = (float*)d_out;

    const int T = 256;

    // Fork: gemm1 is fully independent -> side stream from t=0.
    cudaEventRecord(g_evA, 0);
    cudaStreamWaitEvent(g_s2, g_evA, 0);
    k_gemm1<<<(NN + 127) / 128, 128, 0, g_s2>>>(x, W1, p_z0, p_y1, NN);
    cudaEventRecord(g_evB, g_s2);

    // Main chain: structure.
    cudaMemsetAsync(p_degcnt, 0, NN * sizeof(ull), 0);
    k_deg<<<(EE / 2 + T - 1) / T, T>>>(ei, w, p_degcnt, p_total, EE / 2);
    k_assign<<<(NN + 255) / 256, 256>>>(p_degcnt, p_base, p_cursor, p_dinv, p_total, NN);
    k_bucket<<<(EE / 2 + T - 1) / T, T>>>(ei, w, p_dinv, p_cursor, p_pack, EE / 2);

    // Join, then gather.
    cudaStreamWaitEvent(0, g_evB, 0);
    k_gather1<<<(NN + 7) / 8, 256>>>(p_base, p_cursor, p_pack, p_y1, p_z0, b1, p_h, NN);
    k_gather2_final<<<(NN + 7) / 8, 256>>>(p_base, p_cursor, p_pack, p_h, W2, b2, out, NN);
}

// round 9
// speedup vs baseline: 2.0954x; 1.0780x over previous
#include <cuda_runtime.h>
#include <cuda_bf16.h>
#include <math.h>

#define NN 100000
#define EE 1600000
#define FIN 64
#define HID 16
#define CC 40
#define CAP 64              // slab capacity per node (P(deg>64) ~ 1e-18)
#define OFMAX 65536         // overflow list capacity (safety net)

typedef unsigned long long ull;

#define DEG_SCALE 33554432.0f   // 2^25 fixed-point for weighted degree
#define DEG_INV   (1.0f / 33554432.0f)

// ---------------- scratch (static device globals; no allocation) ----------------
__device__ ull   d_degcnt[NN];        // (cnt:int32 << 32) | fixed25(sum w)
__device__ float d_dinv[NN];          // rsqrt(deg)
__device__ ull   d_slab[(size_t)NN * CAP];  // per-node edge slab: (src, w) packed
__device__ ull   d_osd[OFMAX];        // overflow: (src, w)
__device__ int   d_odst[OFMAX];       // overflow: dst
__device__ int   d_ocnt[1];           // overflow count
__device__ float d_z0[NN * HID];      // x @ W1[0]
__device__ float d_y1[NN * HID];      // x @ W1[1]; scaled in place to dinv*y1 by k_node
__device__ float d_h[NN * HID];       // relu(z0 - dinv*acc + b1)  (unscaled)
__device__ float d_hs[NN * HID];      // dinv * h (gather table for layer 2)

static ull*   p_degcnt;
static float* p_dinv;
static ull*   p_slab;
static ull*   p_osd;   static int* p_odst;  static int* p_ocnt;
static float* p_z0;    static float* p_y1;  static float* p_h;  static float* p_hs;
static cudaStream_t g_s2;
static cudaEvent_t  g_evA, g_evB;

// ---------------- kernels ----------------
// ONE edge pass: fused 64-bit atomic gives slot (hi32 ++) and accumulates
// fixed-point weighted degree (lo32). Slab write is the only other memory op.
__global__ void k_build(const int* __restrict__ ei, const float* __restrict__ w,
                        ull* degcnt, ull* slab, ull* osd, int* odst, int* ocnt,
                        int n2) {
    int t = blockIdx.x * blockDim.x + threadIdx.x;
    if (t >= n2) return;
    int2   ss = reinterpret_cast<const int2*>(ei)[t];        // src row
    int2   dd = reinterpret_cast<const int2*>(ei + EE)[t];   // dst row
    float2 ww = reinterpret_cast<const float2*>(w)[t];

    ull a0 = (1ULL << 32) | (ull)__float2uint_rn(ww.x * DEG_SCALE);
    ull old0 = atomicAdd(&degcnt[dd.x], a0);
    int slot0 = (int)(old0 >> 32);
    ull p0 = (ull)(unsigned)ss.x | ((ull)__float_as_uint(ww.x) << 32);
    if (slot0 < CAP) slab[(size_t)dd.x * CAP + slot0] = p0;
    else { int o = atomicAdd(ocnt, 1); if (o < OFMAX) { osd[o] = p0; odst[o] = dd.x; } }

    ull a1 = (1ULL << 32) | (ull)__float2uint_rn(ww.y * DEG_SCALE);
    ull old1 = atomicAdd(&degcnt[dd.y], a1);
    int slot1 = (int)(old1 >> 32);
    ull p1 = (ull)(unsigned)ss.y | ((ull)__float_as_uint(ww.y) << 32);
    if (slot1 < CAP) slab[(size_t)dd.y * CAP + slot1] = p1;
    else { int o = atomicAdd(ocnt, 1); if (o < OFMAX) { osd[o] = p1; odst[o] = dd.y; } }
}

// Per node: dinv = rsqrt(deg); y1 *= dinv (in place; gemm1 rewrites each replay).
__global__ void k_node(const ull* __restrict__ degcnt, float* dinv, float* y1, int n) {
    int i = blockIdx.x * blockDim.x + threadIdx.x;
    if (i >= n) return;
    float dg = (float)(unsigned)(degcnt[i] & 0xffffffffULL) * DEG_INV;
    float dv = (dg > 0.0f) ? rsqrtf(dg) : 0.0f;
    dinv[i] = dv;
    float4* y = reinterpret_cast<float4*>(y1 + (size_t)i * HID);
#pragma unroll
    for (int q = 0; q < HID / 4; q++) {
        float4 v = y[q];
        v.x *= dv; v.y *= dv; v.z *= dv; v.w *= dv;
        y[q] = v;
    }
}

// z0 = x@W1[0], y1 = x@W1[1], fused (reads x once). Fully independent ->
// forked on side stream at t=0, hidden under the structure chain.
__global__ void __launch_bounds__(128, 1)
k_gemm1(const float* __restrict__ x, const float* __restrict__ W1,
        float* z0g, float* y1g, int n) {
    __shared__ float W0s[FIN * HID];
    __shared__ float W1s[FIN * HID];
    for (int i = threadIdx.x; i < FIN * HID; i += blockDim.x) {
        W0s[i] = W1[i];
        W1s[i] = W1[FIN * HID + i];
    }
    __syncthreads();
    int nd = blockIdx.x * blockDim.x + threadIdx.x;
    if (nd >= n) return;

    float acc0[HID], acc1[HID];
#pragma unroll
    for (int h = 0; h < HID; h++) { acc0[h] = 0.0f; acc1[h] = 0.0f; }

    const float4* xr = reinterpret_cast<const float4*>(x + (size_t)nd * FIN);
#pragma unroll
    for (int k4 = 0; k4 < FIN / 4; k4++) {
        float4 v = xr[k4];
        const float* w0 = &W0s[(k4 * 4) * HID];
        const float* w1 = &W1s[(k4 * 4) * HID];
#pragma unroll
        for (int h = 0; h < HID; h++) {
            acc0[h] += v.x * w0[h] + v.y * w0[HID + h] + v.z * w0[2 * HID + h] + v.w * w0[3 * HID + h];
            acc1[h] += v.x * w1[h] + v.y * w1[HID + h] + v.z * w1[2 * HID + h] + v.w * w1[3 * HID + h];
        }
    }
    float4* z0 = reinterpret_cast<float4*>(z0g + (size_t)nd * HID);
    float4* y1 = reinterpret_cast<float4*>(y1g + (size_t)nd * HID);
#pragma unroll
    for (int q = 0; q < HID / 4; q++) {
        z0[q] = make_float4(acc0[4 * q], acc0[4 * q + 1], acc0[4 * q + 2], acc0[4 * q + 3]);
        y1[q] = make_float4(acc1[4 * q], acc1[4 * q + 1], acc1[4 * q + 2], acc1[4 * q + 3]);
    }
}

// Gather layer 1: warp per node over the node's slab. Coalesced slab fetch
// (one edge per lane), shuffle-broadcast (src,w); 16-lane group g handles
// edges 2j+g; lane's feature f = lane&15.
// h = relu(z0 - dinv[nd]*acc + b1);  hs = dinv[nd]*h.
__global__ void __launch_bounds__(256, 8)
k_gather1(const ull* __restrict__ degcnt, const ull* __restrict__ slab,
          const ull* __restrict__ osd, const int* __restrict__ odst,
          const int* __restrict__ ocnt,
          const float* __restrict__ y1s, const float* __restrict__ z0,
          const float* __restrict__ b1, const float* __restrict__ dinv,
          float* __restrict__ h, float* __restrict__ hs, int n) {
    int warp = threadIdx.x >> 5;
    int lane = threadIdx.x & 31;
    int nd = blockIdx.x * 8 + warp;
    if (nd >= n) return;

    int cnt = (int)(degcnt[nd] >> 32);
    int m = cnt < CAP ? cnt : CAP;
    size_t sb = (size_t)nd * CAP;
    int g = lane >> 4, f = lane & 15;

    float acc = 0.0f;
    for (int c = 0; c < m; c += 32) {
        int idx = c + lane;
        ull p = (idx < m) ? slab[sb + idx] : 0ULL;   // OOB -> src=0, w=0
        int   srcl = (int)(unsigned)(p & 0xffffffffULL);
        float wl   = __uint_as_float((unsigned)(p >> 32));
        int rem = m - c; if (rem > 32) rem = 32;
        int jmax = (rem + 1) >> 1;                   // warp-uniform
#pragma unroll 4
        for (int j = 0; j < jmax; j++) {
            int sl = 2 * j + g;
            int   src = __shfl_sync(0xffffffffu, srcl, sl);
            float wv  = __shfl_sync(0xffffffffu, wl, sl);
            acc += wv * __ldg(&y1s[(size_t)src * HID + f]);
        }
    }
    acc += __shfl_xor_sync(0xffffffffu, acc, 16);

    if (g == 0) {
        if (cnt > CAP) {                              // ~never taken
            int oc = *ocnt; if (oc > OFMAX) oc = OFMAX;
            for (int i = 0; i < oc; i++) {
                if (odst[i] == nd) {
                    ull p = osd[i];
                    int src = (int)(unsigned)(p & 0xffffffffULL);
                    float wv = __uint_as_float((unsigned)(p >> 32));
                    acc += wv * y1s[(size_t)src * HID + f];
                }
            }
        }
        float dv = dinv[nd];
        float v = z0[(size_t)nd * HID + f] - dv * acc + __ldg(&b1[f]);
        v = fmaxf(v, 0.0f);
        h[(size_t)nd * HID + f] = v;
        hs[(size_t)nd * HID + f] = dv * v;
    }
}

// Gather layer 2 fused with final GEMM + log_softmax. Warp per node.
__global__ void __launch_bounds__(256, 8)
k_gather2_final(const ull* __restrict__ degcnt, const ull* __restrict__ slab,
                const ull* __restrict__ osd, const int* __restrict__ odst,
                const int* __restrict__ ocnt,
                const float* __restrict__ hsg, const float* __restrict__ hg,
                const float* __restrict__ dinv,
                const float* __restrict__ W2, const float* __restrict__ b2,
                float* __restrict__ out, int n) {
    __shared__ float W20s[HID * CC];
    __shared__ float W21s[HID * CC];
    __shared__ float b2s[CC];
    for (int i = threadIdx.x; i < HID * CC; i += blockDim.x) {
        W20s[i] = W2[i];
        W21s[i] = W2[HID * CC + i];
    }
    if (threadIdx.x < CC) b2s[threadIdx.x] = b2[threadIdx.x];
    __syncthreads();

    int warp = threadIdx.x >> 5;
    int lane = threadIdx.x & 31;
    int nd = blockIdx.x * 8 + warp;
    if (nd >= n) return;

    int cnt = (int)(degcnt[nd] >> 32);
    int m = cnt < CAP ? cnt : CAP;
    size_t sb = (size_t)nd * CAP;
    int g = lane >> 4, f = lane & 15;

    float acc = 0.0f;
    for (int c = 0; c < m; c += 32) {
        int idx = c + lane;
        ull p = (idx < m) ? slab[sb + idx] : 0ULL;
        int   srcl = (int)(unsigned)(p & 0xffffffffULL);
        float wl   = __uint_as_float((unsigned)(p >> 32));
        int rem = m - c; if (rem > 32) rem = 32;
        int jmax = (rem + 1) >> 1;
#pragma unroll 4
        for (int j = 0; j < jmax; j++) {
            int sl = 2 * j + g;
            int   src = __shfl_sync(0xffffffffu, srcl, sl);
            float wv  = __shfl_sync(0xffffffffu, wl, sl);
            acc += wv * __ldg(&hsg[(size_t)src * HID + f]);
        }
    }
    acc += __shfl_xor_sync(0xffffffffu, acc, 16);
    if (g == 0 && cnt > CAP) {                        // ~never taken
        int oc = *ocnt; if (oc > OFMAX) oc = OFMAX;
        for (int i = 0; i < oc; i++) {
            if (odst[i] == nd) {
                ull p = osd[i];
                int src = (int)(unsigned)(p & 0xffffffffULL);
                float wv = __uint_as_float((unsigned)(p >> 32));
                acc += wv * hsg[(size_t)src * HID + f];
            }
        }
    }
    acc *= -dinv[nd];   // Tx1 feature f valid in lanes 0..15 (only ones read below)

    const float* hp = hg + (size_t)nd * HID;
    float oa = b2s[lane];                               // class = lane
    float ob = (lane < CC - 32) ? b2s[32 + lane] : 0.f; // class = lane+32
#pragma unroll
    for (int ff = 0; ff < HID; ff++) {
        float hf = hp[ff];                               // warp-uniform broadcast
        float af = __shfl_sync(0xffffffffu, acc, ff);    // lane ff holds feature ff
        oa += hf * W20s[ff * CC + lane] + af * W21s[ff * CC + lane];
        if (lane < CC - 32)
            ob += hf * W20s[ff * CC + 32 + lane] + af * W21s[ff * CC + 32 + lane];
    }

    float mx = (lane < CC - 32) ? fmaxf(oa, ob) : oa;
#pragma unroll
    for (int off = 16; off > 0; off >>= 1)
        mx = fmaxf(mx, __shfl_xor_sync(0xffffffffu, mx, off));

    float sexp = expf(oa - mx) + ((lane < CC - 32) ? expf(ob - mx) : 0.0f);
#pragma unroll
    for (int off = 16; off > 0; off >>= 1)
        sexp += __shfl_xor_sync(0xffffffffu, sexp, off);

    float lse = logf(sexp) + mx;

    float* op = out + (size_t)nd * CC;
    op[lane] = oa - lse;
    if (lane < CC - 32) op[32 + lane] = ob - lse;
}

// ---------------- prewarm ----------------
namespace {
struct Prewarm {
    Prewarm() {
        void* p;
        cudaGetSymbolAddress(&p, d_degcnt); p_degcnt = (ull*)p;
        cudaGetSymbolAddress(&p, d_dinv);   p_dinv   = (float*)p;
        cudaGetSymbolAddress(&p, d_slab);   p_slab   = (ull*)p;
        cudaGetSymbolAddress(&p, d_osd);    p_osd    = (ull*)p;
        cudaGetSymbolAddress(&p, d_odst);   p_odst   = (int*)p;
        cudaGetSymbolAddress(&p, d_ocnt);   p_ocnt   = (int*)p;
        cudaGetSymbolAddress(&p, d_z0);     p_z0     = (float*)p;
        cudaGetSymbolAddress(&p, d_y1);     p_y1     = (float*)p;
        cudaGetSymbolAddress(&p, d_h);      p_h      = (float*)p;
        cudaGetSymbolAddress(&p, d_hs);     p_hs     = (float*)p;

        cudaStreamCreateWithFlags(&g_s2, cudaStreamNonBlocking);
        cudaEventCreateWithFlags(&g_evA, cudaEventDisableTiming);
        cudaEventCreateWithFlags(&g_evB, cudaEventDisableTiming);

        // Degenerate launches to force module/code load + lmem pool sizing
        // before the harness checkpoint. All pointers valid; n=0 guards.
        const int*   di = (const int*)p_odst;
        const float* df = (const float*)p_z0;
        cudaMemsetAsync(p_degcnt, 0, NN * sizeof(ull), 0);
        cudaMemsetAsync(p_ocnt, 0, sizeof(int), 0);
        k_build<<<1, 32>>>(di, df, p_degcnt, p_slab, p_osd, p_odst, p_ocnt, 0);
        k_node<<<1, 32>>>(p_degcnt, p_dinv, p_y1, 0);
        k_gemm1<<<1, 128, 0, g_s2>>>(df, df, p_z0, p_y1, 0);
        k_gather1<<<1, 256>>>(p_degcnt, p_slab, p_osd, p_odst, p_ocnt,
                              p_y1, p_z0, df, p_dinv, p_h, p_hs, 0);
        k_gather2_final<<<1, 256>>>(p_degcnt, p_slab, p_osd, p_odst, p_ocnt,
                                    p_hs, p_h, p_dinv, df, df, p_z0, 0);
        cudaDeviceSynchronize();
    }
};
Prewarm g_prewarm;
}  // namespace

// ---------------- launch ----------------
extern "C" void kernel_launch(void* const* d_in, const int* in_sizes, int n_in,
                              void* d_out, int out_size) {
    const float* x  = (const float*)d_in[0];
    const float* w  = (const float*)d_in[1];
    const float* W1 = (const float*)d_in[2];
    const float* b1 = (const float*)d_in[3];
    const float* W2 = (const float*)d_in[4];
    const float* b2 = (const float*)d_in[5];
    const int*   ei = (const int*)d_in[6];
    float* out = (float*)d_out;

    const int T = 256;

    // Fork: gemm1 is fully independent -> side stream from t=0.
    cudaEventRecord(g_evA, 0);
    cudaStreamWaitEvent(g_s2, g_evA, 0);
    k_gemm1<<<(NN + 127) / 128, 128, 0, g_s2>>>(x, W1, p_z0, p_y1, NN);
    cudaEventRecord(g_evB, g_s2);

    // Main chain: ONE edge pass builds slabs + weighted degrees.
    cudaMemsetAsync(p_degcnt, 0, NN * sizeof(ull), 0);
    cudaMemsetAsync(p_ocnt, 0, sizeof(int), 0);
    k_build<<<(EE / 2 + T - 1) / T, T>>>(ei, w, p_degcnt, p_slab, p_osd, p_odst, p_ocnt, EE / 2);

    // Join gemm1, then per-node dinv + y1 scaling, then gathers.
    cudaStreamWaitEvent(0, g_evB, 0);
    k_node<<<(NN + T - 1) / T, T>>>(p_degcnt, p_dinv, p_y1, NN);
    k_gather1<<<(NN + 7) / 8, 256>>>(p_degcnt, p_slab, p_osd, p_odst, p_ocnt,
                                     p_y1, p_z0, b1, p_dinv, p_h, p_hs, NN);
    k_gather2_final<<<(NN + 7) / 8, 256>>>(p_degcnt, p_slab, p_osd, p_odst, p_ocnt,
                                           p_hs, p_h, p_dinv, W2, b2, out, NN);
}